// round 2
// baseline (speedup 1.0000x reference)
#include <cuda_runtime.h>
#include <cuda_bf16.h>
#include <math.h>

// Problem shape
#define BB 4
#define TT 2048
#define DD 1024
#define HH 16
#define PP 64
#define FFD 4096
#define ROWS (BB*TT)          // 8192

// ---------------- scratch (device globals; no allocation allowed) -------------
__device__ float g_nX [ROWS*DD];
__device__ float g_Q  [ROWS*DD];
__device__ float g_K  [ROWS*DD];
__device__ float g_V  [ROWS*DD];
__device__ float g_NV [ROWS*DD];
__device__ float g_SS [ROWS*DD];
__device__ float g_PRE[ROWS*DD];
__device__ float g_HID[ROWS*FFD];

__device__ __forceinline__ float gelu_f(float x) {
    return 0.5f * x * (1.0f + erff(x * 0.70710678118654752440f));
}

// ---------------- LayerNorm (optionally + residual added AFTER LN) ------------
// Y[row] = (res ? res[row] : 0) + LN(X[row]) * g + b
__global__ void ln_kernel(const float* __restrict__ X, const float* __restrict__ gg,
                          const float* __restrict__ bb, float* __restrict__ Y,
                          const float* __restrict__ res)
{
    __shared__ float s1[256], s2[256];
    const int row = blockIdx.x;
    const int t = threadIdx.x;
    const float4* xr = (const float4*)(X + (size_t)row * DD);
    float4 v = xr[t];
    float s = v.x + v.y + v.z + v.w;
    float q = v.x*v.x + v.y*v.y + v.z*v.z + v.w*v.w;
    s1[t] = s; s2[t] = q;
    __syncthreads();
    #pragma unroll
    for (int o = 128; o > 0; o >>= 1) {
        if (t < o) { s1[t] += s1[t+o]; s2[t] += s2[t+o]; }
        __syncthreads();
    }
    const float mu  = s1[0] * (1.0f/1024.0f);
    const float var = s2[0] * (1.0f/1024.0f) - mu*mu;
    const float inv = rsqrtf(var + 1e-5f);
    float4 g4 = ((const float4*)gg)[t];
    float4 b4 = ((const float4*)bb)[t];
    float4 o;
    o.x = (v.x-mu)*inv*g4.x + b4.x;
    o.y = (v.y-mu)*inv*g4.y + b4.y;
    o.z = (v.z-mu)*inv*g4.z + b4.z;
    o.w = (v.w-mu)*inv*g4.w + b4.w;
    if (res) {
        float4 r = ((const float4*)(res + (size_t)row * DD))[t];
        o.x += r.x; o.y += r.y; o.z += r.z; o.w += r.w;
    }
    ((float4*)(Y + (size_t)row * DD))[t] = o;
}

// ---------------- generic tiled SGEMM: C = act(A@B + bias) + residual --------
// A: [M,K] row-major. bLayout: 0 -> B row-major [K,N];
//                              1 -> B is [H, K, 64] (col = h*64+p)  (WQ/WK/WV layout)
__global__ void gemm64x64(const float* __restrict__ A, const float* __restrict__ B,
                          float* __restrict__ C, int M, int N, int K, int bLayout,
                          const float* __restrict__ bias,
                          const float* __restrict__ residual, int act)
{
    __shared__ float As[16][68];
    __shared__ float Bs[16][64];
    const int tx = threadIdx.x, ty = threadIdx.y;
    const int tid = ty * 16 + tx;
    const int row0 = blockIdx.y * 64;
    const int col0 = blockIdx.x * 64;
    float acc[4][4] = {};

    for (int k0 = 0; k0 < K; k0 += 16) {
        #pragma unroll
        for (int i = 0; i < 4; i++) {
            int idx = tid + i * 256;
            int m = idx >> 4, kk = idx & 15;
            As[kk][m] = A[(size_t)(row0 + m) * K + k0 + kk];
        }
        #pragma unroll
        for (int i = 0; i < 4; i++) {
            int idx = tid + i * 256;
            int kk = idx >> 6, n = idx & 63;
            int col = col0 + n;
            float v;
            if (bLayout == 0) v = B[(size_t)(k0 + kk) * N + col];
            else              v = B[(size_t)(col >> 6) * K * 64 + (size_t)(k0 + kk) * 64 + (col & 63)];
            Bs[kk][n] = v;
        }
        __syncthreads();
        #pragma unroll
        for (int kk = 0; kk < 16; kk++) {
            float4 a4 = *(const float4*)&As[kk][ty * 4];
            float4 b4 = *(const float4*)&Bs[kk][tx * 4];
            float a[4] = {a4.x, a4.y, a4.z, a4.w};
            float b[4] = {b4.x, b4.y, b4.z, b4.w};
            #pragma unroll
            for (int i = 0; i < 4; i++)
                #pragma unroll
                for (int j = 0; j < 4; j++)
                    acc[i][j] += a[i] * b[j];
        }
        __syncthreads();
    }
    #pragma unroll
    for (int i = 0; i < 4; i++) {
        int row = row0 + ty * 4 + i;
        #pragma unroll
        for (int j = 0; j < 4; j++) {
            int col = col0 + tx * 4 + j;
            float v = acc[i][j];
            if (bias)     v += bias[col];
            if (act)      v  = gelu_f(v);
            if (residual) v += residual[(size_t)row * N + col];
            C[(size_t)row * N + col] = v;
        }
    }
}

// ---------------- scores: S[b,h,q,k] = (K[b,q,h,:] . Q[b,k,h,:]) / sqrt(P) ----
// NOTE: reference swaps q/k (queries carry index k).
__global__ void scores_kernel(const float* __restrict__ Kmat, const float* __restrict__ Qmat,
                              float* __restrict__ S)
{
    const int bh = blockIdx.z;
    const int b = bh >> 4, h = bh & 15;
    const int q0 = blockIdx.y * 64;
    const int kc0 = blockIdx.x * 64;
    const int tx = threadIdx.x, ty = threadIdx.y;
    const int tid = ty * 16 + tx;
    __shared__ float As[16][68];
    __shared__ float Bs[16][68];
    float acc[4][4] = {};
    const float* Kh = Kmat + (size_t)b * TT * DD + h * PP;
    const float* Qh = Qmat + (size_t)b * TT * DD + h * PP;

    #pragma unroll
    for (int p0 = 0; p0 < PP; p0 += 16) {
        #pragma unroll
        for (int i = 0; i < 4; i++) {
            int idx = tid + i * 256;
            int m = idx >> 4, kk = idx & 15;
            As[kk][m] = Kh[(size_t)(q0 + m) * DD + p0 + kk];
        }
        #pragma unroll
        for (int i = 0; i < 4; i++) {
            int idx = tid + i * 256;
            int m = idx >> 4, kk = idx & 15;
            Bs[kk][m] = Qh[(size_t)(kc0 + m) * DD + p0 + kk];
        }
        __syncthreads();
        #pragma unroll
        for (int kk = 0; kk < 16; kk++) {
            float4 a4 = *(const float4*)&As[kk][ty * 4];
            float4 b4 = *(const float4*)&Bs[kk][tx * 4];
            float a[4] = {a4.x, a4.y, a4.z, a4.w};
            float bv[4] = {b4.x, b4.y, b4.z, b4.w};
            #pragma unroll
            for (int i = 0; i < 4; i++)
                #pragma unroll
                for (int j = 0; j < 4; j++)
                    acc[i][j] += a[i] * bv[j];
        }
        __syncthreads();
    }
    #pragma unroll
    for (int i = 0; i < 4; i++) {
        int q = q0 + ty * 4 + i;
        #pragma unroll
        for (int j = 0; j < 4; j++) {
            int k = kc0 + tx * 4 + j;
            S[((size_t)bh * TT + q) * TT + k] = acc[i][j] * 0.125f;  // 1/sqrt(64)
        }
    }
}

// ---------------- in-place row softmax over last axis (row length 2048) ------
__global__ void softmax_kernel(float* __restrict__ S)
{
    __shared__ float red[256];
    const size_t row = blockIdx.x;
    float* p = S + row * (size_t)TT;
    const int t = threadIdx.x;
    float v[8];
    float mx = -1e30f;
    #pragma unroll
    for (int i = 0; i < 8; i++) { v[i] = p[t + i * 256]; mx = fmaxf(mx, v[i]); }
    red[t] = mx; __syncthreads();
    #pragma unroll
    for (int o = 128; o > 0; o >>= 1) {
        if (t < o) red[t] = fmaxf(red[t], red[t+o]);
        __syncthreads();
    }
    mx = red[0];
    __syncthreads();
    float sum = 0.0f;
    #pragma unroll
    for (int i = 0; i < 8; i++) { v[i] = __expf(v[i] - mx); sum += v[i]; }
    red[t] = sum; __syncthreads();
    #pragma unroll
    for (int o = 128; o > 0; o >>= 1) {
        if (t < o) red[t] += red[t+o];
        __syncthreads();
    }
    const float inv = 1.0f / red[0];
    #pragma unroll
    for (int i = 0; i < 8; i++) p[t + i * 256] = v[i] * inv;
}

// ---------------- NV[b,q,h,p] = sum_k attn[b,h,q,k] * V[b,k,h,p] --------------
__global__ void av_kernel(const float* __restrict__ Attn, const float* __restrict__ Vmat,
                          float* __restrict__ NV)
{
    const int bh = blockIdx.y;
    const int b = bh >> 4, h = bh & 15;
    const int q0 = blockIdx.x * 64;
    const int tx = threadIdx.x, ty = threadIdx.y;
    const int tid = ty * 16 + tx;
    __shared__ float As[16][68];
    __shared__ float Bs[16][64];
    float acc[4][4] = {};
    const float* Ah = Attn + (size_t)bh * TT * TT;
    const float* Vh = Vmat + (size_t)b * TT * DD + h * PP;

    for (int k0 = 0; k0 < TT; k0 += 16) {
        #pragma unroll
        for (int i = 0; i < 4; i++) {
            int idx = tid + i * 256;
            int m = idx >> 4, kk = idx & 15;
            As[kk][m] = Ah[(size_t)(q0 + m) * TT + k0 + kk];
        }
        #pragma unroll
        for (int i = 0; i < 4; i++) {
            int idx = tid + i * 256;
            int kk = idx >> 6, n = idx & 63;
            Bs[kk][n] = Vh[(size_t)(k0 + kk) * DD + n];
        }
        __syncthreads();
        #pragma unroll
        for (int kk = 0; kk < 16; kk++) {
            float4 a4 = *(const float4*)&As[kk][ty * 4];
            float4 b4 = *(const float4*)&Bs[kk][tx * 4];
            float a[4] = {a4.x, a4.y, a4.z, a4.w};
            float bv[4] = {b4.x, b4.y, b4.z, b4.w};
            #pragma unroll
            for (int i = 0; i < 4; i++)
                #pragma unroll
                for (int j = 0; j < 4; j++)
                    acc[i][j] += a[i] * bv[j];
        }
        __syncthreads();
    }
    #pragma unroll
    for (int i = 0; i < 4; i++) {
        int q = q0 + ty * 4 + i;
        #pragma unroll
        for (int j = 0; j < 4; j++) {
            int pcol = tx * 4 + j;
            NV[(size_t)(b * TT + q) * DD + h * PP + pcol] = acc[i][j];
        }
    }
}

// -----------------------------------------------------------------------------
extern "C" void kernel_launch(void* const* d_in, const int* in_sizes, int n_in,
                              void* d_out, int out_size)
{
    const float* X      = (const float*)d_in[0];
    const float* WQ     = (const float*)d_in[1];
    const float* WK     = (const float*)d_in[2];
    const float* WV     = (const float*)d_in[3];
    const float* WO     = (const float*)d_in[4];
    const float* attn_g = (const float*)d_in[5];
    const float* attn_b = (const float*)d_in[6];
    const float* ff_g   = (const float*)d_in[7];
    const float* ff_b   = (const float*)d_in[8];
    const float* fW1    = (const float*)d_in[9];
    const float* fb1    = (const float*)d_in[10];
    const float* fW2    = (const float*)d_in[11];
    const float* fb2    = (const float*)d_in[12];

    float* out1 = (float*)d_out;                               // [B,T,D]
    float* attn = (float*)d_out + (size_t)BB * TT * DD;        // [B,H,T,T]

    float *nX, *Q, *K_, *V, *NV, *SS, *PRE, *HID;
    cudaGetSymbolAddress((void**)&nX,  g_nX);
    cudaGetSymbolAddress((void**)&Q,   g_Q);
    cudaGetSymbolAddress((void**)&K_,  g_K);
    cudaGetSymbolAddress((void**)&V,   g_V);
    cudaGetSymbolAddress((void**)&NV,  g_NV);
    cudaGetSymbolAddress((void**)&SS,  g_SS);
    cudaGetSymbolAddress((void**)&PRE, g_PRE);
    cudaGetSymbolAddress((void**)&HID, g_HID);

    dim3 blk(16, 16);

    // 1. nX = LN(X)
    ln_kernel<<<ROWS, 256>>>(X, attn_g, attn_b, nX, nullptr);

    // 2-4. Q/K/V = nX @ W{Q,K,V}   (weights in [H,D,P] layout -> bLayout=1)
    gemm64x64<<<dim3(DD/64, ROWS/64), blk>>>(nX, WQ, Q,  ROWS, DD, DD, 1, nullptr, nullptr, 0);
    gemm64x64<<<dim3(DD/64, ROWS/64), blk>>>(nX, WK, K_, ROWS, DD, DD, 1, nullptr, nullptr, 0);
    gemm64x64<<<dim3(DD/64, ROWS/64), blk>>>(nX, WV, V,  ROWS, DD, DD, 1, nullptr, nullptr, 0);

    // 5. scores -> attn region of d_out (raw), then 6. softmax in place
    scores_kernel<<<dim3(TT/64, TT/64, BB*HH), blk>>>(K_, Q, attn);
    softmax_kernel<<<BB*HH*TT, 256>>>(attn);

    // 7. new_values = attn @ V
    av_kernel<<<dim3(TT/64, BB*HH), blk>>>(attn, V, NV);

    // 8. seq_summary = NV @ WO   (WO is [H,P,D] == row-major [1024,1024])
    gemm64x64<<<dim3(DD/64, ROWS/64), blk>>>(NV, WO, SS, ROWS, DD, DD, 0, nullptr, nullptr, 0);

    // 9. pre_ff = X + LN(seq_summary)
    ln_kernel<<<ROWS, 256>>>(SS, ff_g, ff_b, PRE, X);

    // 10. hidden = gelu(pre_ff @ fW1 + fb1)
    gemm64x64<<<dim3(FFD/64, ROWS/64), blk>>>(PRE, fW1, HID, ROWS, FFD, DD, 0, fb1, nullptr, 1);

    // 11. out1 = hidden @ fW2 + fb2 + pre_ff
    gemm64x64<<<dim3(DD/64, ROWS/64), blk>>>(HID, fW2, out1, ROWS, DD, FFD, 0, fb2, PRE, 0);
}

// round 3
// speedup vs baseline: 1.0253x; 1.0253x over previous
#include <cuda_runtime.h>
#include <cuda_bf16.h>
#include <math.h>

// Problem shape
#define BB 4
#define TT 2048
#define DD 1024
#define HH 16
#define PP 64
#define FFD 4096
#define ROWS (BB*TT)          // 8192

// ---------------- scratch (device globals; no allocation allowed) -------------
__device__ float g_nX [ROWS*DD];
__device__ float g_Q  [ROWS*DD];
__device__ float g_K  [ROWS*DD];
__device__ float g_V  [ROWS*DD];
__device__ float g_NV [ROWS*DD];
__device__ float g_SS [ROWS*DD];
__device__ float g_PRE[ROWS*DD];
__device__ float g_HID[ROWS*FFD];

__device__ __forceinline__ float gelu_f(float x) {
    return 0.5f * x * (1.0f + erff(x * 0.70710678118654752440f));
}

// ---------------- LayerNorm (optionally + residual added AFTER LN) ------------
__global__ void ln_kernel(const float* __restrict__ X, const float* __restrict__ gg,
                          const float* __restrict__ bb, float* __restrict__ Y,
                          const float* __restrict__ res)
{
    __shared__ float s1[256], s2[256];
    const int row = blockIdx.x;
    const int t = threadIdx.x;
    const float4* xr = (const float4*)(X + (size_t)row * DD);
    float4 v = xr[t];
    float s = v.x + v.y + v.z + v.w;
    float q = v.x*v.x + v.y*v.y + v.z*v.z + v.w*v.w;
    s1[t] = s; s2[t] = q;
    __syncthreads();
    #pragma unroll
    for (int o = 128; o > 0; o >>= 1) {
        if (t < o) { s1[t] += s1[t+o]; s2[t] += s2[t+o]; }
        __syncthreads();
    }
    const float mu  = s1[0] * (1.0f/1024.0f);
    const float var = s2[0] * (1.0f/1024.0f) - mu*mu;
    const float inv = rsqrtf(var + 1e-5f);
    float4 g4 = ((const float4*)gg)[t];
    float4 b4 = ((const float4*)bb)[t];
    float4 o;
    o.x = (v.x-mu)*inv*g4.x + b4.x;
    o.y = (v.y-mu)*inv*g4.y + b4.y;
    o.z = (v.z-mu)*inv*g4.z + b4.z;
    o.w = (v.w-mu)*inv*g4.w + b4.w;
    if (res) {
        float4 r = ((const float4*)(res + (size_t)row * DD))[t];
        o.x += r.x; o.y += r.y; o.z += r.z; o.w += r.w;
    }
    ((float4*)(Y + (size_t)row * DD))[t] = o;
}

// =====================================================================
// 128x128 tiled SGEMM, BK=8, 8x8 microtile, double-buffered smem.
// C = act(A@B + bias) + residual
// bLayout: 0 -> B row-major [K,N]; 1 -> B is [H,K,64], col = h*64+p
// Requires M%128==0, N%128==0, K%8==0.
// =====================================================================
__global__ void __launch_bounds__(256) sgemm128(
    const float* __restrict__ A, const float* __restrict__ B, float* __restrict__ C,
    int M, int N, int K, int bLayout,
    const float* __restrict__ bias, const float* __restrict__ residual, int act)
{
    __shared__ float As[2][8][128];
    __shared__ float Bs[2][8][128];
    const int tid = threadIdx.x;
    const int row0 = blockIdx.y * 128;
    const int col0 = blockIdx.x * 128;

    // A load: 128x8 tile, conflict-free transposed store
    const int aRow = tid & 127;
    const int aCol = (tid >> 7) * 4;
    // B load: 8x128 tile, direct float4 store
    const int bRow = tid >> 5;
    const int bCol = (tid & 31) * 4;
    // compute microtile
    const int tRow = (tid >> 4) * 8;
    const int tCol = (tid & 15) * 8;

    const float* Abase = A + (size_t)(row0 + aRow) * K + aCol;
    const float* Bbase;
    size_t bstride;
    if (bLayout == 0) {
        Bbase = B + (size_t)bRow * N + col0 + bCol;
        bstride = (size_t)N;
    } else {
        int col = col0 + bCol;
        Bbase = B + (size_t)(col >> 6) * ((size_t)K * 64) + (size_t)bRow * 64 + (col & 63);
        bstride = 64;
    }

    float acc[8][8] = {};

    // preload panel 0
    float4 aR = *(const float4*)(Abase);
    float4 bR = *(const float4*)(Bbase);
    As[0][aCol+0][aRow]=aR.x; As[0][aCol+1][aRow]=aR.y;
    As[0][aCol+2][aRow]=aR.z; As[0][aCol+3][aRow]=aR.w;
    *(float4*)&Bs[0][bRow][bCol] = bR;
    __syncthreads();

    const int nT = K >> 3;
    int buf = 0;
    for (int t = 0; t < nT; t++) {
        if (t + 1 < nT) {
            aR = *(const float4*)(Abase + (t + 1) * 8);
            bR = *(const float4*)(Bbase + (size_t)(t + 1) * 8 * bstride);
        }
        #pragma unroll
        for (int k = 0; k < 8; k++) {
            float4 a0 = *(const float4*)&As[buf][k][tRow];
            float4 a1 = *(const float4*)&As[buf][k][tRow+4];
            float4 b0 = *(const float4*)&Bs[buf][k][tCol];
            float4 b1 = *(const float4*)&Bs[buf][k][tCol+4];
            float a[8]  = {a0.x,a0.y,a0.z,a0.w,a1.x,a1.y,a1.z,a1.w};
            float bb[8] = {b0.x,b0.y,b0.z,b0.w,b1.x,b1.y,b1.z,b1.w};
            #pragma unroll
            for (int i = 0; i < 8; i++)
                #pragma unroll
                for (int j = 0; j < 8; j++)
                    acc[i][j] += a[i] * bb[j];
        }
        if (t + 1 < nT) {
            buf ^= 1;
            As[buf][aCol+0][aRow]=aR.x; As[buf][aCol+1][aRow]=aR.y;
            As[buf][aCol+2][aRow]=aR.z; As[buf][aCol+3][aRow]=aR.w;
            *(float4*)&Bs[buf][bRow][bCol] = bR;
            __syncthreads();
        }
    }

    // epilogue
    float bv[8];
    #pragma unroll
    for (int j = 0; j < 8; j++) bv[j] = bias ? bias[col0 + tCol + j] : 0.0f;

    #pragma unroll
    for (int i = 0; i < 8; i++) {
        int row = row0 + tRow + i;
        float* crow = C + (size_t)row * N + col0 + tCol;
        float v[8];
        #pragma unroll
        for (int j = 0; j < 8; j++) {
            float x = acc[i][j] + bv[j];
            if (act) x = gelu_f(x);
            v[j] = x;
        }
        if (residual) {
            const float* rrow = residual + (size_t)row * N + col0 + tCol;
            float4 r0 = *(const float4*)rrow;
            float4 r1 = *(const float4*)(rrow + 4);
            v[0]+=r0.x; v[1]+=r0.y; v[2]+=r0.z; v[3]+=r0.w;
            v[4]+=r1.x; v[5]+=r1.y; v[6]+=r1.z; v[7]+=r1.w;
        }
        *(float4*)crow       = make_float4(v[0],v[1],v[2],v[3]);
        *(float4*)(crow + 4) = make_float4(v[4],v[5],v[6],v[7]);
    }
}

// =====================================================================
// scores: S[b,h,q,k] = (K[b,q,h,:] . Q[b,k,h,:]) / 8   (reference swaps q/k)
// 128x128 tile over (q,k), K-dim = P = 64.
// =====================================================================
__global__ void __launch_bounds__(256) scores128(
    const float* __restrict__ Kmat, const float* __restrict__ Qmat, float* __restrict__ S)
{
    const int bh = blockIdx.z;
    const int b = bh >> 4, h = bh & 15;
    const int q0 = blockIdx.y * 128;
    const int c0 = blockIdx.x * 128;
    const float* Kh = Kmat + (size_t)b * TT * DD + h * PP;
    const float* Qh = Qmat + (size_t)b * TT * DD + h * PP;

    __shared__ float As[2][8][128];
    __shared__ float Bs[2][8][128];
    const int tid = threadIdx.x;
    const int aRow = tid & 127;
    const int aCol = (tid >> 7) * 4;
    const int tRow = (tid >> 4) * 8;
    const int tCol = (tid & 15) * 8;

    const float* Ab = Kh + (size_t)(q0 + aRow) * DD + aCol;
    const float* Bb = Qh + (size_t)(c0 + aRow) * DD + aCol;

    float acc[8][8] = {};

    float4 aR = *(const float4*)Ab;
    float4 bR = *(const float4*)Bb;
    As[0][aCol+0][aRow]=aR.x; As[0][aCol+1][aRow]=aR.y;
    As[0][aCol+2][aRow]=aR.z; As[0][aCol+3][aRow]=aR.w;
    Bs[0][aCol+0][aRow]=bR.x; Bs[0][aCol+1][aRow]=bR.y;
    Bs[0][aCol+2][aRow]=bR.z; Bs[0][aCol+3][aRow]=bR.w;
    __syncthreads();

    int buf = 0;
    #pragma unroll
    for (int t = 0; t < 8; t++) {   // 64 / 8
        if (t + 1 < 8) {
            aR = *(const float4*)(Ab + (t + 1) * 8);
            bR = *(const float4*)(Bb + (t + 1) * 8);
        }
        #pragma unroll
        for (int k = 0; k < 8; k++) {
            float4 a0 = *(const float4*)&As[buf][k][tRow];
            float4 a1 = *(const float4*)&As[buf][k][tRow+4];
            float4 b0 = *(const float4*)&Bs[buf][k][tCol];
            float4 b1 = *(const float4*)&Bs[buf][k][tCol+4];
            float a[8]  = {a0.x,a0.y,a0.z,a0.w,a1.x,a1.y,a1.z,a1.w};
            float bb[8] = {b0.x,b0.y,b0.z,b0.w,b1.x,b1.y,b1.z,b1.w};
            #pragma unroll
            for (int i = 0; i < 8; i++)
                #pragma unroll
                for (int j = 0; j < 8; j++)
                    acc[i][j] += a[i] * bb[j];
        }
        if (t + 1 < 8) {
            buf ^= 1;
            As[buf][aCol+0][aRow]=aR.x; As[buf][aCol+1][aRow]=aR.y;
            As[buf][aCol+2][aRow]=aR.z; As[buf][aCol+3][aRow]=aR.w;
            Bs[buf][aCol+0][aRow]=bR.x; Bs[buf][aCol+1][aRow]=bR.y;
            Bs[buf][aCol+2][aRow]=bR.z; Bs[buf][aCol+3][aRow]=bR.w;
            __syncthreads();
        }
    }

    #pragma unroll
    for (int i = 0; i < 8; i++) {
        int q = q0 + tRow + i;
        float* srow = S + ((size_t)bh * TT + q) * TT + c0 + tCol;
        *(float4*)srow = make_float4(acc[i][0]*0.125f, acc[i][1]*0.125f,
                                     acc[i][2]*0.125f, acc[i][3]*0.125f);
        *(float4*)(srow + 4) = make_float4(acc[i][4]*0.125f, acc[i][5]*0.125f,
                                           acc[i][6]*0.125f, acc[i][7]*0.125f);
    }
}

// ---------------- in-place row softmax over last axis (row length 2048) ------
__global__ void softmax_kernel(float* __restrict__ S)
{
    __shared__ float red[256];
    const size_t row = blockIdx.x;
    float* p = S + row * (size_t)TT;
    const int t = threadIdx.x;
    float v[8];
    float mx = -1e30f;
    #pragma unroll
    for (int i = 0; i < 8; i++) { v[i] = p[t + i * 256]; mx = fmaxf(mx, v[i]); }
    red[t] = mx; __syncthreads();
    #pragma unroll
    for (int o = 128; o > 0; o >>= 1) {
        if (t < o) red[t] = fmaxf(red[t], red[t+o]);
        __syncthreads();
    }
    mx = red[0];
    __syncthreads();
    float sum = 0.0f;
    #pragma unroll
    for (int i = 0; i < 8; i++) { v[i] = __expf(v[i] - mx); sum += v[i]; }
    red[t] = sum; __syncthreads();
    #pragma unroll
    for (int o = 128; o > 0; o >>= 1) {
        if (t < o) red[t] += red[t+o];
        __syncthreads();
    }
    const float inv = 1.0f / red[0];
    #pragma unroll
    for (int i = 0; i < 8; i++) p[t + i * 256] = v[i] * inv;
}

// =====================================================================
// AV: NV[b,q,h,p] = sum_k attn[b,h,q,k] * V[b,k,h,p]
// 128x64 tile (q x p), BK=8, 8x8 microtile, 128 threads, double-buffered.
// =====================================================================
__global__ void __launch_bounds__(128) av128(
    const float* __restrict__ Attn, const float* __restrict__ Vmat, float* __restrict__ NV)
{
    const int bh = blockIdx.y;
    const int b = bh >> 4, h = bh & 15;
    const int q0 = blockIdx.x * 128;
    const float* Ah = Attn + (size_t)bh * TT * TT;
    const float* Vh = Vmat + (size_t)b * TT * DD + h * PP;

    __shared__ float As[2][8][128];
    __shared__ float Bs[2][8][64];
    const int tid = threadIdx.x;
    // A: 128x8 tile; thread = one row, loads 8 contiguous k
    const float* Ab = Ah + (size_t)(q0 + tid) * TT;
    // B: 8x64 tile
    const int bRow = tid >> 4;
    const int bCol = (tid & 15) * 4;
    const float* Bb = Vh + (size_t)bRow * DD + bCol;
    // compute microtile 8x8: 16 x 8 thread grid
    const int tRow = (tid >> 3) * 8;
    const int tCol = (tid & 7) * 8;

    float acc[8][8] = {};

    float4 aR0 = *(const float4*)(Ab);
    float4 aR1 = *(const float4*)(Ab + 4);
    float4 bR  = *(const float4*)(Bb);
    As[0][0][tid]=aR0.x; As[0][1][tid]=aR0.y; As[0][2][tid]=aR0.z; As[0][3][tid]=aR0.w;
    As[0][4][tid]=aR1.x; As[0][5][tid]=aR1.y; As[0][6][tid]=aR1.z; As[0][7][tid]=aR1.w;
    *(float4*)&Bs[0][bRow][bCol] = bR;
    __syncthreads();

    const int nT = TT >> 3;  // 256
    int buf = 0;
    for (int t = 0; t < nT; t++) {
        if (t + 1 < nT) {
            aR0 = *(const float4*)(Ab + (t + 1) * 8);
            aR1 = *(const float4*)(Ab + (t + 1) * 8 + 4);
            bR  = *(const float4*)(Bb + (size_t)(t + 1) * 8 * DD);
        }
        #pragma unroll
        for (int k = 0; k < 8; k++) {
            float4 a0 = *(const float4*)&As[buf][k][tRow];
            float4 a1 = *(const float4*)&As[buf][k][tRow+4];
            float4 b0 = *(const float4*)&Bs[buf][k][tCol];
            float4 b1 = *(const float4*)&Bs[buf][k][tCol+4];
            float a[8]  = {a0.x,a0.y,a0.z,a0.w,a1.x,a1.y,a1.z,a1.w};
            float bb[8] = {b0.x,b0.y,b0.z,b0.w,b1.x,b1.y,b1.z,b1.w};
            #pragma unroll
            for (int i = 0; i < 8; i++)
                #pragma unroll
                for (int j = 0; j < 8; j++)
                    acc[i][j] += a[i] * bb[j];
        }
        if (t + 1 < nT) {
            buf ^= 1;
            As[buf][0][tid]=aR0.x; As[buf][1][tid]=aR0.y; As[buf][2][tid]=aR0.z; As[buf][3][tid]=aR0.w;
            As[buf][4][tid]=aR1.x; As[buf][5][tid]=aR1.y; As[buf][6][tid]=aR1.z; As[buf][7][tid]=aR1.w;
            *(float4*)&Bs[buf][bRow][bCol] = bR;
            __syncthreads();
        }
    }

    #pragma unroll
    for (int i = 0; i < 8; i++) {
        int q = q0 + tRow + i;
        float* nrow = NV + (size_t)(b * TT + q) * DD + h * PP + tCol;
        *(float4*)nrow       = make_float4(acc[i][0],acc[i][1],acc[i][2],acc[i][3]);
        *(float4*)(nrow + 4) = make_float4(acc[i][4],acc[i][5],acc[i][6],acc[i][7]);
    }
}

// -----------------------------------------------------------------------------
extern "C" void kernel_launch(void* const* d_in, const int* in_sizes, int n_in,
                              void* d_out, int out_size)
{
    const float* X      = (const float*)d_in[0];
    const float* WQ     = (const float*)d_in[1];
    const float* WK     = (const float*)d_in[2];
    const float* WV     = (const float*)d_in[3];
    const float* WO     = (const float*)d_in[4];
    const float* attn_g = (const float*)d_in[5];
    const float* attn_b = (const float*)d_in[6];
    const float* ff_g   = (const float*)d_in[7];
    const float* ff_b   = (const float*)d_in[8];
    const float* fW1    = (const float*)d_in[9];
    const float* fb1    = (const float*)d_in[10];
    const float* fW2    = (const float*)d_in[11];
    const float* fb2    = (const float*)d_in[12];

    float* out1 = (float*)d_out;                               // [B,T,D]
    float* attn = (float*)d_out + (size_t)BB * TT * DD;        // [B,H,T,T]

    float *nX, *Q, *K_, *V, *NV, *SS, *PRE, *HID;
    cudaGetSymbolAddress((void**)&nX,  g_nX);
    cudaGetSymbolAddress((void**)&Q,   g_Q);
    cudaGetSymbolAddress((void**)&K_,  g_K);
    cudaGetSymbolAddress((void**)&V,   g_V);
    cudaGetSymbolAddress((void**)&NV,  g_NV);
    cudaGetSymbolAddress((void**)&SS,  g_SS);
    cudaGetSymbolAddress((void**)&PRE, g_PRE);
    cudaGetSymbolAddress((void**)&HID, g_HID);

    // 1. nX = LN(X)
    ln_kernel<<<ROWS, 256>>>(X, attn_g, attn_b, nX, nullptr);

    // 2-4. Q/K/V = nX @ W{Q,K,V}   (weights in [H,D,P] layout -> bLayout=1)
    dim3 gQKV(DD/128, ROWS/128);
    sgemm128<<<gQKV, 256>>>(nX, WQ, Q,  ROWS, DD, DD, 1, nullptr, nullptr, 0);
    sgemm128<<<gQKV, 256>>>(nX, WK, K_, ROWS, DD, DD, 1, nullptr, nullptr, 0);
    sgemm128<<<gQKV, 256>>>(nX, WV, V,  ROWS, DD, DD, 1, nullptr, nullptr, 0);

    // 5. scores -> attn region of d_out (raw), then 6. softmax in place
    scores128<<<dim3(TT/128, TT/128, BB*HH), 256>>>(K_, Q, attn);
    softmax_kernel<<<BB*HH*TT, 256>>>(attn);

    // 7. new_values = attn @ V
    av128<<<dim3(TT/128, BB*HH), 128>>>(attn, V, NV);

    // 8. seq_summary = NV @ WO   (WO is [H,P,D] == row-major [1024,1024])
    sgemm128<<<dim3(DD/128, ROWS/128), 256>>>(NV, WO, SS, ROWS, DD, DD, 0, nullptr, nullptr, 0);

    // 9. pre_ff = X + LN(seq_summary)
    ln_kernel<<<ROWS, 256>>>(SS, ff_g, ff_b, PRE, X);

    // 10. hidden = gelu(pre_ff @ fW1 + fb1)
    sgemm128<<<dim3(FFD/128, ROWS/128), 256>>>(PRE, fW1, HID, ROWS, FFD, DD, 0, fb1, nullptr, 1);

    // 11. out1 = hidden @ fW2 + fb2 + pre_ff
    sgemm128<<<dim3(DD/128, ROWS/128), 256>>>(HID, fW2, out1, ROWS, DD, FFD, 0, fb2, PRE, 0);
}

// round 5
// speedup vs baseline: 2.5721x; 2.5086x over previous
#include <cuda_runtime.h>
#include <cuda_bf16.h>
#include <math.h>
#include <stdint.h>
#include <cstdint>

// Problem shape
#define BB 4
#define TT 2048
#define DD 1024
#define HH 16
#define PP 64
#define FFD 4096
#define ROWS (BB*TT)          // 8192

// ---------------- scratch (device globals; no allocation allowed) -------------
__device__ float g_nX [ROWS*DD];
__device__ float g_Q  [ROWS*DD];
__device__ float g_K  [ROWS*DD];
__device__ float g_V  [ROWS*DD];
__device__ float g_NV [ROWS*DD];
__device__ float g_SS [ROWS*DD];
__device__ float g_PRE[ROWS*DD];
__device__ float g_HID[ROWS*FFD];

__device__ __forceinline__ float gelu_f(float x) {
    return 0.5f * x * (1.0f + erff(x * 0.70710678118654752440f));
}

__device__ __forceinline__ uint32_t f2tf32(float x) {
    uint32_t u;
    asm("cvt.rna.tf32.f32 %0, %1;" : "=r"(u) : "f"(x));
    return u;
}

__device__ __forceinline__ void mma8(float* c, const uint32_t* a, uint32_t b0, uint32_t b1) {
    asm volatile(
        "mma.sync.aligned.m16n8k8.row.col.f32.tf32.tf32.f32 "
        "{%0,%1,%2,%3}, {%4,%5,%6,%7}, {%8,%9}, {%0,%1,%2,%3};\n"
        : "+f"(c[0]), "+f"(c[1]), "+f"(c[2]), "+f"(c[3])
        : "r"(a[0]), "r"(a[1]), "r"(a[2]), "r"(a[3]), "r"(b0), "r"(b1));
}

// ---------------- LayerNorm (optionally + residual added AFTER LN) ------------
__global__ void ln_kernel(const float* __restrict__ X, const float* __restrict__ gg,
                          const float* __restrict__ bb, float* __restrict__ Y,
                          const float* __restrict__ res)
{
    __shared__ float s1[256], s2[256];
    const int row = blockIdx.x;
    const int t = threadIdx.x;
    const float4* xr = (const float4*)(X + (size_t)row * DD);
    float4 v = xr[t];
    float s = v.x + v.y + v.z + v.w;
    float q = v.x*v.x + v.y*v.y + v.z*v.z + v.w*v.w;
    s1[t] = s; s2[t] = q;
    __syncthreads();
    #pragma unroll
    for (int o = 128; o > 0; o >>= 1) {
        if (t < o) { s1[t] += s1[t+o]; s2[t] += s2[t+o]; }
        __syncthreads();
    }
    const float mu  = s1[0] * (1.0f/1024.0f);
    const float var = s2[0] * (1.0f/1024.0f) - mu*mu;
    const float inv = rsqrtf(var + 1e-5f);
    float4 g4 = ((const float4*)gg)[t];
    float4 b4 = ((const float4*)bb)[t];
    float4 o;
    o.x = (v.x-mu)*inv*g4.x + b4.x;
    o.y = (v.y-mu)*inv*g4.y + b4.y;
    o.z = (v.z-mu)*inv*g4.z + b4.z;
    o.w = (v.w-mu)*inv*g4.w + b4.w;
    if (res) {
        float4 r = ((const float4*)(res + (size_t)row * DD))[t];
        o.x += r.x; o.y += r.y; o.z += r.z; o.w += r.w;
    }
    ((float4*)(Y + (size_t)row * DD))[t] = o;
}

// ---------------- in-place row softmax over last axis (row length 2048) ------
__global__ void softmax_kernel(float* __restrict__ S)
{
    __shared__ float red[256];
    const size_t row = blockIdx.x;
    float* p = S + row * (size_t)TT;
    const int t = threadIdx.x;
    float v[8];
    float mx = -1e30f;
    #pragma unroll
    for (int i = 0; i < 8; i++) { v[i] = p[t + i * 256]; mx = fmaxf(mx, v[i]); }
    red[t] = mx; __syncthreads();
    #pragma unroll
    for (int o = 128; o > 0; o >>= 1) {
        if (t < o) red[t] = fmaxf(red[t], red[t+o]);
        __syncthreads();
    }
    mx = red[0];
    __syncthreads();
    float sum = 0.0f;
    #pragma unroll
    for (int i = 0; i < 8; i++) { v[i] = __expf(v[i] - mx); sum += v[i]; }
    red[t] = sum; __syncthreads();
    #pragma unroll
    for (int o = 128; o > 0; o >>= 1) {
        if (t < o) red[t] += red[t+o];
        __syncthreads();
    }
    const float inv = 1.0f / red[0];
    #pragma unroll
    for (int i = 0; i < 8; i++) p[t + i * 256] = v[i] * inv;
}

// =====================================================================
// Unified tf32 tensor-core GEMM.
//   C[r][c] = act( scale * sum_k A[r][k]*B(k,c) + bias[c] ) + residual[r][c]
// BM=128 fixed, BK=32, 256 threads, warp grid 2(m) x 4(n).
// BMODE: 0 -> B row-major [K,N] (ldb = row stride)
//        1 -> B is [H, K, 64], global col = h*64+p (QKV weights)
//        2 -> B given as [N, K] row-major (ldb = row stride)  [scores]
// grid.z decomposed as z = 16*zb + zh; per-matrix offsets offB/offH applied.
// =====================================================================
template<int BN, int BMODE>
__global__ void __launch_bounds__(256) mma_gemm(
    const float* __restrict__ A, int lda, size_t aOffB, size_t aOffH,
    const float* __restrict__ B, int ldb, size_t bOffB, size_t bOffH,
    float*       __restrict__ C, int ldc, size_t cOffB, size_t cOffH,
    int K, const float* __restrict__ bias, const float* __restrict__ residual,
    int act, float scale)
{
    constexpr int BM = 128, BK = 32;
    constexpr int NT = BN / 32;        // n-tiles (of 8) per warp
    constexpr int WN = BN / 4;         // warp n extent

    __shared__ uint32_t As[BM][BK + 4];        // [m][k], pad 36
    __shared__ uint32_t Bs[BK][BN + 4];        // [k][n], pad +4

    const int tid  = threadIdx.x;
    const int lane = tid & 31;
    const int warp = tid >> 5;
    const int g  = lane >> 2;          // group id 0..7
    const int tq = lane & 3;           // thread-in-group 0..3
    const int wmBase = (warp & 1) * 64;
    const int wnBase = (warp >> 1) * WN;

    const int row0 = blockIdx.y * BM;
    const int col0 = blockIdx.x * BN;

    const int zb = blockIdx.z >> 4, zh = blockIdx.z & 15;
    A += (size_t)zb * aOffB + (size_t)zh * aOffH;
    B += (size_t)zb * bOffB + (size_t)zh * bOffH;
    C += (size_t)zb * cOffB + (size_t)zh * cOffH;

    // loader index precompute
    const int arow = tid >> 3;              // 0..31 (+32*p)
    const int ac4  = (tid & 7) * 4;
    int bk0, bn4;                            // mode 0/1 B mapping
    if (BN == 128) { bk0 = tid >> 5; bn4 = (tid & 31) * 4; }
    else           { bk0 = tid >> 4; bn4 = (tid & 15) * 4; }
    const int bkstep = (BN == 128) ? 8 : 16;
    const int bpasses = (BN == 128) ? 4 : 2;

    float4 aP[4], bP[4];

    auto loadPanel = [&](int k0) {
        #pragma unroll
        for (int p = 0; p < 4; p++)
            aP[p] = *(const float4*)(A + (size_t)(row0 + arow + 32*p) * lda + k0 + ac4);
        if (BMODE == 2) {
            #pragma unroll
            for (int p = 0; p < 4; p++)
                bP[p] = *(const float4*)(B + (size_t)(col0 + arow + 32*p) * ldb + k0 + ac4);
        } else if (BMODE == 0) {
            #pragma unroll
            for (int p = 0; p < bpasses; p++)
                bP[p] = *(const float4*)(B + (size_t)(k0 + bk0 + bkstep*p) * ldb + col0 + bn4);
        } else { // HDP
            #pragma unroll
            for (int p = 0; p < bpasses; p++) {
                int col = col0 + bn4;
                bP[p] = *(const float4*)(B + (size_t)(col >> 6) * ((size_t)K * 64)
                                           + (size_t)(k0 + bk0 + bkstep*p) * 64 + (col & 63));
            }
        }
    };

    auto storePanel = [&]() {
        #pragma unroll
        for (int p = 0; p < 4; p++) {
            uint4 u = make_uint4(f2tf32(aP[p].x), f2tf32(aP[p].y), f2tf32(aP[p].z), f2tf32(aP[p].w));
            *(uint4*)&As[arow + 32*p][ac4] = u;
        }
        if (BMODE == 2) {
            #pragma unroll
            for (int p = 0; p < 4; p++) {
                int n = arow + 32*p;
                Bs[ac4+0][n] = f2tf32(bP[p].x);
                Bs[ac4+1][n] = f2tf32(bP[p].y);
                Bs[ac4+2][n] = f2tf32(bP[p].z);
                Bs[ac4+3][n] = f2tf32(bP[p].w);
            }
        } else {
            #pragma unroll
            for (int p = 0; p < bpasses; p++) {
                uint4 u = make_uint4(f2tf32(bP[p].x), f2tf32(bP[p].y), f2tf32(bP[p].z), f2tf32(bP[p].w));
                *(uint4*)&Bs[bk0 + bkstep*p][bn4] = u;
            }
        }
    };

    float acc[4][NT][4];
    #pragma unroll
    for (int i = 0; i < 4; i++)
        #pragma unroll
        for (int j = 0; j < NT; j++)
            #pragma unroll
            for (int l = 0; l < 4; l++) acc[i][j][l] = 0.0f;

    const int nT = K >> 5;
    loadPanel(0);
    storePanel();
    __syncthreads();

    for (int t = 0; t < nT; t++) {
        if (t + 1 < nT) loadPanel((t + 1) * BK);

        #pragma unroll
        for (int ks = 0; ks < 4; ks++) {
            const int kb = ks * 8;
            uint32_t af[4][4];
            #pragma unroll
            for (int mi = 0; mi < 4; mi++) {
                int r = wmBase + mi * 16 + g;
                af[mi][0] = As[r    ][kb + tq];
                af[mi][1] = As[r + 8][kb + tq];
                af[mi][2] = As[r    ][kb + tq + 4];
                af[mi][3] = As[r + 8][kb + tq + 4];
            }
            #pragma unroll
            for (int ni = 0; ni < NT; ni++) {
                int n = wnBase + ni * 8 + g;
                uint32_t b0 = Bs[kb + tq    ][n];
                uint32_t b1 = Bs[kb + tq + 4][n];
                #pragma unroll
                for (int mi = 0; mi < 4; mi++)
                    mma8(acc[mi][ni], af[mi], b0, b1);
            }
        }

        if (t + 1 < nT) {
            __syncthreads();
            storePanel();
            __syncthreads();
        }
    }

    // ---------------- epilogue ----------------
    #pragma unroll
    for (int mi = 0; mi < 4; mi++) {
        int r0 = row0 + wmBase + mi * 16 + g;
        #pragma unroll
        for (int ni = 0; ni < NT; ni++) {
            int col = col0 + wnBase + ni * 8 + 2 * tq;
            float b0 = 0.0f, b1 = 0.0f;
            if (bias) { b0 = bias[col]; b1 = bias[col + 1]; }
            #pragma unroll
            for (int half = 0; half < 2; half++) {
                int r = r0 + half * 8;
                float x0 = acc[mi][ni][half*2 + 0] * scale + b0;
                float x1 = acc[mi][ni][half*2 + 1] * scale + b1;
                if (act) { x0 = gelu_f(x0); x1 = gelu_f(x1); }
                if (residual) {
                    float2 rr = *(const float2*)(residual + (size_t)r * ldc + col);
                    x0 += rr.x; x1 += rr.y;
                }
                *(float2*)(C + (size_t)r * ldc + col) = make_float2(x0, x1);
            }
        }
    }
}

// -----------------------------------------------------------------------------
extern "C" void kernel_launch(void* const* d_in, const int* in_sizes, int n_in,
                              void* d_out, int out_size)
{
    const float* X      = (const float*)d_in[0];
    const float* WQ     = (const float*)d_in[1];
    const float* WK     = (const float*)d_in[2];
    const float* WV     = (const float*)d_in[3];
    const float* WO     = (const float*)d_in[4];
    const float* attn_g = (const float*)d_in[5];
    const float* attn_b = (const float*)d_in[6];
    const float* ff_g   = (const float*)d_in[7];
    const float* ff_b   = (const float*)d_in[8];
    const float* fW1    = (const float*)d_in[9];
    const float* fb1    = (const float*)d_in[10];
    const float* fW2    = (const float*)d_in[11];
    const float* fb2    = (const float*)d_in[12];

    float* out1 = (float*)d_out;                               // [B,T,D]
    float* attn = (float*)d_out + (size_t)BB * TT * DD;        // [B,H,T,T]

    float *nX, *Q, *K_, *V, *NV, *SS, *PRE, *HID;
    cudaGetSymbolAddress((void**)&nX,  g_nX);
    cudaGetSymbolAddress((void**)&Q,   g_Q);
    cudaGetSymbolAddress((void**)&K_,  g_K);
    cudaGetSymbolAddress((void**)&V,   g_V);
    cudaGetSymbolAddress((void**)&NV,  g_NV);
    cudaGetSymbolAddress((void**)&SS,  g_SS);
    cudaGetSymbolAddress((void**)&PRE, g_PRE);
    cudaGetSymbolAddress((void**)&HID, g_HID);

    const size_t TT2 = (size_t)TT * TT;
    const size_t TD  = (size_t)TT * DD;

    // 1. nX = LN(X)
    ln_kernel<<<ROWS, 256>>>(X, attn_g, attn_b, nX, nullptr);

    // 2-4. Q/K/V = nX @ W{Q,K,V}   (weights in [H,D,P] layout -> BMODE=1)
    dim3 gQKV(DD/128, ROWS/128, 1);
    mma_gemm<128,1><<<gQKV, 256>>>(nX, DD, 0,0, WQ, 0, 0,0, Q,  DD, 0,0, DD, nullptr, nullptr, 0, 1.0f);
    mma_gemm<128,1><<<gQKV, 256>>>(nX, DD, 0,0, WK, 0, 0,0, K_, DD, 0,0, DD, nullptr, nullptr, 0, 1.0f);
    mma_gemm<128,1><<<gQKV, 256>>>(nX, DD, 0,0, WV, 0, 0,0, V,  DD, 0,0, DD, nullptr, nullptr, 0, 1.0f);

    // 5. scores: S[bh][q][k] = (K[b,q,h,:].Q[b,k,h,:]) / 8   (reference swaps q/k)
    mma_gemm<128,2><<<dim3(TT/128, TT/128, BB*HH), 256>>>(
        K_, DD, TD, 64,
        Q,  DD, TD, 64,
        attn, TT, 16*TT2, TT2,
        PP, nullptr, nullptr, 0, 0.125f);

    // 6. softmax in place
    softmax_kernel<<<BB*HH*TT, 256>>>(attn);

    // 7. new_values: NV[b,q,h,:] = sum_k attn[bh][q][k] * V[b,k,h,:]
    mma_gemm<64,0><<<dim3(1, TT/128, BB*HH), 256>>>(
        attn, TT, 16*TT2, TT2,
        V,    DD, TD, 64,
        NV,   DD, TD, 64,
        TT, nullptr, nullptr, 0, 1.0f);

    // 8. seq_summary = NV @ WO   (WO is [H,P,D] == row-major [1024,1024])
    mma_gemm<128,0><<<dim3(DD/128, ROWS/128, 1), 256>>>(
        NV, DD, 0,0, WO, DD, 0,0, SS, DD, 0,0, DD, nullptr, nullptr, 0, 1.0f);

    // 9. pre_ff = X + LN(seq_summary)
    ln_kernel<<<ROWS, 256>>>(SS, ff_g, ff_b, PRE, X);

    // 10. hidden = gelu(pre_ff @ fW1 + fb1)
    mma_gemm<128,0><<<dim3(FFD/128, ROWS/128, 1), 256>>>(
        PRE, DD, 0,0, fW1, FFD, 0,0, HID, FFD, 0,0, DD, fb1, nullptr, 1, 1.0f);

    // 11. out1 = hidden @ fW2 + fb2 + pre_ff
    mma_gemm<128,0><<<dim3(DD/128, ROWS/128, 1), 256>>>(
        HID, FFD, 0,0, fW2, DD, 0,0, out1, DD, 0,0, FFD, fb2, PRE, 0, 1.0f);
}

// round 6
// speedup vs baseline: 3.1867x; 1.2390x over previous
#include <cuda_runtime.h>
#include <cuda_bf16.h>
#include <math.h>
#include <stdint.h>
#include <cstdint>

// Problem shape
#define BB 4
#define TT 2048
#define DD 1024
#define HH 16
#define PP 64
#define FFD 4096
#define ROWS (BB*TT)          // 8192

// ---------------- scratch (device globals; no allocation allowed) -------------
__device__ float g_nX [ROWS*DD];
__device__ float g_Q  [ROWS*DD];
__device__ float g_K  [ROWS*DD];
__device__ float g_V  [ROWS*DD];
__device__ float g_NV [ROWS*DD];
__device__ float g_SS [ROWS*DD];
__device__ float g_PRE[ROWS*DD];
__device__ float g_HID[ROWS*FFD];

__device__ __forceinline__ float gelu_f(float x) {
    return 0.5f * x * (1.0f + erff(x * 0.70710678118654752440f));
}

__device__ __forceinline__ uint32_t f2tf32(float x) {
    uint32_t u;
    asm("cvt.rna.tf32.f32 %0, %1;" : "=r"(u) : "f"(x));
    return u;
}

__device__ __forceinline__ void mma8(float* c, const uint32_t* a, uint32_t b0, uint32_t b1) {
    asm volatile(
        "mma.sync.aligned.m16n8k8.row.col.f32.tf32.tf32.f32 "
        "{%0,%1,%2,%3}, {%4,%5,%6,%7}, {%8,%9}, {%0,%1,%2,%3};\n"
        : "+f"(c[0]), "+f"(c[1]), "+f"(c[2]), "+f"(c[3])
        : "r"(a[0]), "r"(a[1]), "r"(a[2]), "r"(a[3]), "r"(b0), "r"(b1));
}

__device__ __forceinline__ void cp16(float* dst, const float* src) {
    uint32_t d = (uint32_t)__cvta_generic_to_shared(dst);
    asm volatile("cp.async.cg.shared.global [%0], [%1], 16;\n" :: "r"(d), "l"(src));
}
__device__ __forceinline__ void cp_commit() {
    asm volatile("cp.async.commit_group;\n");
}
__device__ __forceinline__ void cp_wait1() {
    asm volatile("cp.async.wait_group 1;\n");
}

// ---------------- LayerNorm (optionally + residual added AFTER LN) ------------
__global__ void ln_kernel(const float* __restrict__ X, const float* __restrict__ gg,
                          const float* __restrict__ bb, float* __restrict__ Y,
                          const float* __restrict__ res)
{
    __shared__ float s1[256], s2[256];
    const int row = blockIdx.x;
    const int t = threadIdx.x;
    const float4* xr = (const float4*)(X + (size_t)row * DD);
    float4 v = xr[t];
    float s = v.x + v.y + v.z + v.w;
    float q = v.x*v.x + v.y*v.y + v.z*v.z + v.w*v.w;
    s1[t] = s; s2[t] = q;
    __syncthreads();
    #pragma unroll
    for (int o = 128; o > 0; o >>= 1) {
        if (t < o) { s1[t] += s1[t+o]; s2[t] += s2[t+o]; }
        __syncthreads();
    }
    const float mu  = s1[0] * (1.0f/1024.0f);
    const float var = s2[0] * (1.0f/1024.0f) - mu*mu;
    const float inv = rsqrtf(var + 1e-5f);
    float4 g4 = ((const float4*)gg)[t];
    float4 b4 = ((const float4*)bb)[t];
    float4 o;
    o.x = (v.x-mu)*inv*g4.x + b4.x;
    o.y = (v.y-mu)*inv*g4.y + b4.y;
    o.z = (v.z-mu)*inv*g4.z + b4.z;
    o.w = (v.w-mu)*inv*g4.w + b4.w;
    if (res) {
        float4 r = ((const float4*)(res + (size_t)row * DD))[t];
        o.x += r.x; o.y += r.y; o.z += r.z; o.w += r.w;
    }
    ((float4*)(Y + (size_t)row * DD))[t] = o;
}

// ---------------- in-place row softmax over last axis (row length 2048) ------
__global__ void softmax_kernel(float* __restrict__ S)
{
    __shared__ float red[256];
    const size_t row = blockIdx.x;
    float* p = S + row * (size_t)TT;
    const int t = threadIdx.x;
    float v[8];
    float mx = -1e30f;
    #pragma unroll
    for (int i = 0; i < 8; i++) { v[i] = p[t + i * 256]; mx = fmaxf(mx, v[i]); }
    red[t] = mx; __syncthreads();
    #pragma unroll
    for (int o = 128; o > 0; o >>= 1) {
        if (t < o) red[t] = fmaxf(red[t], red[t+o]);
        __syncthreads();
    }
    mx = red[0];
    __syncthreads();
    float sum = 0.0f;
    #pragma unroll
    for (int i = 0; i < 8; i++) { v[i] = __expf(v[i] - mx); sum += v[i]; }
    red[t] = sum; __syncthreads();
    #pragma unroll
    for (int o = 128; o > 0; o >>= 1) {
        if (t < o) red[t] += red[t+o];
        __syncthreads();
    }
    const float inv = 1.0f / red[0];
    #pragma unroll
    for (int i = 0; i < 8; i++) p[t + i * 256] = v[i] * inv;
}

// =====================================================================
// Unified tf32 tensor-core GEMM, 3-stage cp.async pipeline.
//   C[r][c] = act( scale * sum_k A[r][k]*B(k,c) + bias[c] ) + residual[r][c]
// BM=128, BK=32, 256 threads, warp grid 2(m) x 4(n), 2 CTAs/SM target.
// BMODE: 0 -> B row-major [K,N]
//        1 -> B is [H, K, 64], global col = h*64+p (QKV weights)
//        2 -> B given as [N, K] row-major (scores; smem tile kept n-major)
// grid.z = 16*zb + zh; per-matrix offsets applied.
// Shared memory is dynamic: STAGES*(A_STAGE + B_STAGE) floats.
// =====================================================================
template<int BN, int BMODE>
__global__ void __launch_bounds__(256, 2) mma_gemm(
    const float* __restrict__ A, int lda, size_t aOffB, size_t aOffH,
    const float* __restrict__ B, int ldb, size_t bOffB, size_t bOffH,
    float*       __restrict__ C, int ldc, size_t cOffB, size_t cOffH,
    int K, const float* __restrict__ bias, const float* __restrict__ residual,
    int act, float scale)
{
    constexpr int BM = 128, BK = 32, STAGES = 3;
    constexpr int NT = BN / 32;        // n-tiles (of 8) per warp
    constexpr int WN = BN / 4;         // warp n extent
    constexpr int AROW = BK + 4;                    // 36 floats
    constexpr int A_STAGE = BM * AROW;              // 4608
    constexpr int BROW = (BMODE == 2) ? (BK + 4) : (BN + 4);
    constexpr int B_STAGE = (BMODE == 2) ? (BN * BROW) : (BK * BROW);

    extern __shared__ float sm[];
    float* AsBase = sm;
    float* BsBase = sm + STAGES * A_STAGE;

    const int tid  = threadIdx.x;
    const int lane = tid & 31;
    const int warp = tid >> 5;
    const int g  = lane >> 2;          // group id 0..7
    const int tq = lane & 3;           // thread-in-group 0..3
    const int wmBase = (warp & 1) * 64;
    const int wnBase = (warp >> 1) * WN;

    const int row0 = blockIdx.y * BM;
    const int col0 = blockIdx.x * BN;

    const int zb = blockIdx.z >> 4, zh = blockIdx.z & 15;
    A += (size_t)zb * aOffB + (size_t)zh * aOffH;
    B += (size_t)zb * bOffB + (size_t)zh * bOffH;
    C += (size_t)zb * cOffB + (size_t)zh * cOffH;

    const int nT = K >> 5;

    // ---- async tile loaders ----
    auto issueA = [&](int t, float* dst) {
        const float* Ak = A + (size_t)row0 * lda + t * BK;
        #pragma unroll
        for (int p = 0; p < 4; p++) {
            int chunk = tid + 256 * p;
            int r = chunk >> 3, c = (chunk & 7) * 4;
            cp16(dst + r * AROW + c, Ak + (size_t)r * lda + c);
        }
    };
    auto issueB = [&](int t, float* dst) {
        if (BMODE == 2) {
            const float* Bk = B + (size_t)col0 * ldb + t * BK;
            #pragma unroll
            for (int p = 0; p < 4; p++) {
                int chunk = tid + 256 * p;
                int r = chunk >> 3, c = (chunk & 7) * 4;
                cp16(dst + r * BROW + c, Bk + (size_t)r * ldb + c);
            }
        } else if (BMODE == 0) {
            constexpr int P   = (BN == 128) ? 4 : 2;
            constexpr int CSH = (BN == 128) ? 5 : 4;
            constexpr int CMK = (BN == 128) ? 31 : 15;
            const float* Bk = B + (size_t)(t * BK) * ldb + col0;
            #pragma unroll
            for (int p = 0; p < P; p++) {
                int chunk = tid + 256 * p;
                int k = chunk >> CSH, c = (chunk & CMK) * 4;
                cp16(dst + k * BROW + c, Bk + (size_t)k * ldb + c);
            }
        } else { // BMODE 1 (HDP), BN==128
            #pragma unroll
            for (int p = 0; p < 4; p++) {
                int chunk = tid + 256 * p;
                int k = chunk >> 5, c = (chunk & 31) * 4;
                int col = col0 + c;
                const float* src = B + (size_t)(col >> 6) * ((size_t)K * 64)
                                     + (size_t)(t * BK + k) * 64 + (col & 63);
                cp16(dst + k * BROW + c, src);
            }
        }
    };

    float acc[4][NT][4];
    #pragma unroll
    for (int i = 0; i < 4; i++)
        #pragma unroll
        for (int j = 0; j < NT; j++)
            #pragma unroll
            for (int l = 0; l < 4; l++) acc[i][j][l] = 0.0f;

    // ---- prologue: issue STAGES-1 panels ----
    #pragma unroll
    for (int t = 0; t < STAGES - 1; t++) {
        if (t < nT) { issueA(t, AsBase + t * A_STAGE); issueB(t, BsBase + t * B_STAGE); }
        cp_commit();
    }

    int s = 0;
    for (int t = 0; t < nT; t++) {
        cp_wait1();
        __syncthreads();

        const float* As = AsBase + s * A_STAGE;
        const float* Bsm = BsBase + s * B_STAGE;

        #pragma unroll
        for (int ks = 0; ks < 4; ks++) {
            const int kb = ks * 8;
            uint32_t af[4][4];
            #pragma unroll
            for (int mi = 0; mi < 4; mi++) {
                int r = wmBase + mi * 16 + g;
                af[mi][0] = f2tf32(As[(size_t)r       * AROW + kb + tq]);
                af[mi][1] = f2tf32(As[(size_t)(r + 8) * AROW + kb + tq]);
                af[mi][2] = f2tf32(As[(size_t)r       * AROW + kb + tq + 4]);
                af[mi][3] = f2tf32(As[(size_t)(r + 8) * AROW + kb + tq + 4]);
            }
            #pragma unroll
            for (int ni = 0; ni < NT; ni++) {
                int n = wnBase + ni * 8 + g;
                uint32_t b0, b1;
                if (BMODE == 2) {
                    b0 = f2tf32(Bsm[(size_t)n * BROW + kb + tq]);
                    b1 = f2tf32(Bsm[(size_t)n * BROW + kb + tq + 4]);
                } else {
                    b0 = f2tf32(Bsm[(size_t)(kb + tq)     * BROW + n]);
                    b1 = f2tf32(Bsm[(size_t)(kb + tq + 4) * BROW + n]);
                }
                #pragma unroll
                for (int mi = 0; mi < 4; mi++)
                    mma8(acc[mi][ni], af[mi], b0, b1);
            }
        }

        __syncthreads();
        int tn = t + STAGES - 1;
        if (tn < nT) {
            int sn = tn - (tn / STAGES) * STAGES;
            issueA(tn, AsBase + sn * A_STAGE);
            issueB(tn, BsBase + sn * B_STAGE);
        }
        cp_commit();

        s++; if (s == STAGES) s = 0;
    }

    // ---------------- epilogue ----------------
    #pragma unroll
    for (int mi = 0; mi < 4; mi++) {
        int r0 = row0 + wmBase + mi * 16 + g;
        #pragma unroll
        for (int ni = 0; ni < NT; ni++) {
            int col = col0 + wnBase + ni * 8 + 2 * tq;
            float b0 = 0.0f, b1 = 0.0f;
            if (bias) { b0 = bias[col]; b1 = bias[col + 1]; }
            #pragma unroll
            for (int half = 0; half < 2; half++) {
                int r = r0 + half * 8;
                float x0 = acc[mi][ni][half*2 + 0] * scale + b0;
                float x1 = acc[mi][ni][half*2 + 1] * scale + b1;
                if (act) { x0 = gelu_f(x0); x1 = gelu_f(x1); }
                if (residual) {
                    float2 rr = *(const float2*)(residual + (size_t)r * ldc + col);
                    x0 += rr.x; x1 += rr.y;
                }
                *(float2*)(C + (size_t)r * ldc + col) = make_float2(x0, x1);
            }
        }
    }
}

// smem sizes (bytes) per instantiation
static constexpr int STAGES_H = 3;
static constexpr size_t smemBytes(int BN, int BMODE) {
    size_t aStage = 128 * 36;
    size_t bStage = (BMODE == 2) ? (size_t)BN * 36 : (size_t)32 * (BN + 4);
    return STAGES_H * (aStage + bStage) * 4;
}

// -----------------------------------------------------------------------------
extern "C" void kernel_launch(void* const* d_in, const int* in_sizes, int n_in,
                              void* d_out, int out_size)
{
    const float* X      = (const float*)d_in[0];
    const float* WQ     = (const float*)d_in[1];
    const float* WK     = (const float*)d_in[2];
    const float* WV     = (const float*)d_in[3];
    const float* WO     = (const float*)d_in[4];
    const float* attn_g = (const float*)d_in[5];
    const float* attn_b = (const float*)d_in[6];
    const float* ff_g   = (const float*)d_in[7];
    const float* ff_b   = (const float*)d_in[8];
    const float* fW1    = (const float*)d_in[9];
    const float* fb1    = (const float*)d_in[10];
    const float* fW2    = (const float*)d_in[11];
    const float* fb2    = (const float*)d_in[12];

    float* out1 = (float*)d_out;                               // [B,T,D]
    float* attn = (float*)d_out + (size_t)BB * TT * DD;        // [B,H,T,T]

    float *nX, *Q, *K_, *V, *NV, *SS, *PRE, *HID;
    cudaGetSymbolAddress((void**)&nX,  g_nX);
    cudaGetSymbolAddress((void**)&Q,   g_Q);
    cudaGetSymbolAddress((void**)&K_,  g_K);
    cudaGetSymbolAddress((void**)&V,   g_V);
    cudaGetSymbolAddress((void**)&NV,  g_NV);
    cudaGetSymbolAddress((void**)&SS,  g_SS);
    cudaGetSymbolAddress((void**)&PRE, g_PRE);
    cudaGetSymbolAddress((void**)&HID, g_HID);

    // opt-in dynamic smem (idempotent, capture-safe)
    static bool attrDone = false;
    if (!attrDone) {
        cudaFuncSetAttribute(mma_gemm<128,1>, cudaFuncAttributeMaxDynamicSharedMemorySize, (int)smemBytes(128,1));
        cudaFuncSetAttribute(mma_gemm<128,2>, cudaFuncAttributeMaxDynamicSharedMemorySize, (int)smemBytes(128,2));
        cudaFuncSetAttribute(mma_gemm<64,0>,  cudaFuncAttributeMaxDynamicSharedMemorySize, (int)smemBytes(64,0));
        cudaFuncSetAttribute(mma_gemm<128,0>, cudaFuncAttributeMaxDynamicSharedMemorySize, (int)smemBytes(128,0));
        attrDone = true;
    }

    const size_t TT2 = (size_t)TT * TT;
    const size_t TD  = (size_t)TT * DD;

    // 1. nX = LN(X)
    ln_kernel<<<ROWS, 256>>>(X, attn_g, attn_b, nX, nullptr);

    // 2-4. Q/K/V = nX @ W{Q,K,V}   (weights in [H,D,P] layout -> BMODE=1)
    dim3 gQKV(DD/128, ROWS/128, 1);
    mma_gemm<128,1><<<gQKV, 256, smemBytes(128,1)>>>(nX, DD, 0,0, WQ, 0, 0,0, Q,  DD, 0,0, DD, nullptr, nullptr, 0, 1.0f);
    mma_gemm<128,1><<<gQKV, 256, smemBytes(128,1)>>>(nX, DD, 0,0, WK, 0, 0,0, K_, DD, 0,0, DD, nullptr, nullptr, 0, 1.0f);
    mma_gemm<128,1><<<gQKV, 256, smemBytes(128,1)>>>(nX, DD, 0,0, WV, 0, 0,0, V,  DD, 0,0, DD, nullptr, nullptr, 0, 1.0f);

    // 5. scores: S[bh][q][k] = (K[b,q,h,:].Q[b,k,h,:]) / 8   (reference swaps q/k)
    mma_gemm<128,2><<<dim3(TT/128, TT/128, BB*HH), 256, smemBytes(128,2)>>>(
        K_, DD, TD, 64,
        Q,  DD, TD, 64,
        attn, TT, 16*TT2, TT2,
        PP, nullptr, nullptr, 0, 0.125f);

    // 6. softmax in place
    softmax_kernel<<<BB*HH*TT, 256>>>(attn);

    // 7. new_values: NV[b,q,h,:] = sum_k attn[bh][q][k] * V[b,k,h,:]
    mma_gemm<64,0><<<dim3(1, TT/128, BB*HH), 256, smemBytes(64,0)>>>(
        attn, TT, 16*TT2, TT2,
        V,    DD, TD, 64,
        NV,   DD, TD, 64,
        TT, nullptr, nullptr, 0, 1.0f);

    // 8. seq_summary = NV @ WO   (WO is [H,P,D] == row-major [1024,1024])
    mma_gemm<128,0><<<dim3(DD/128, ROWS/128, 1), 256, smemBytes(128,0)>>>(
        NV, DD, 0,0, WO, DD, 0,0, SS, DD, 0,0, DD, nullptr, nullptr, 0, 1.0f);

    // 9. pre_ff = X + LN(seq_summary)
    ln_kernel<<<ROWS, 256>>>(SS, ff_g, ff_b, PRE, X);

    // 10. hidden = gelu(pre_ff @ fW1 + fb1)
    mma_gemm<128,0><<<dim3(FFD/128, ROWS/128, 1), 256, smemBytes(128,0)>>>(
        PRE, DD, 0,0, fW1, FFD, 0,0, HID, FFD, 0,0, DD, fb1, nullptr, 1, 1.0f);

    // 11. out1 = hidden @ fW2 + fb2 + pre_ff
    mma_gemm<128,0><<<dim3(DD/128, ROWS/128, 1), 256, smemBytes(128,0)>>>(
        HID, FFD, 0,0, fW2, DD, 0,0, out1, DD, 0,0, FFD, fb2, PRE, 0, 1.0f);
}

// round 7
// speedup vs baseline: 3.6841x; 1.1561x over previous
#include <cuda_runtime.h>
#include <cuda_bf16.h>
#include <math.h>
#include <stdint.h>
#include <cstdint>

// Problem shape
#define BB 4
#define TT 2048
#define DD 1024
#define HH 16
#define PP 64
#define FFD 4096
#define ROWS (BB*TT)          // 8192

// ---------------- scratch (device globals; no allocation allowed) -------------
__device__ float g_nX  [ROWS*DD];
__device__ float g_Q   [ROWS*DD];
__device__ float g_K   [ROWS*DD];
__device__ float g_V   [ROWS*DD];
__device__ float g_NV  [ROWS*DD];
__device__ float g_SS  [ROWS*DD];
__device__ float g_PRE [ROWS*DD];
__device__ float g_PREr[ROWS*DD];
__device__ float g_HID [ROWS*FFD];
__device__ float g_WTS [12*1024*1024];   // rounded weights: WQ|WK|WV|WO|fW1|fW2

__device__ __forceinline__ float gelu_f(float x) {
    return 0.5f * x * (1.0f + erff(x * 0.70710678118654752440f));
}

__device__ __forceinline__ uint32_t f2tf32(float x) {
    uint32_t u;
    asm("cvt.rna.tf32.f32 %0, %1;" : "=r"(u) : "f"(x));
    return u;
}
__device__ __forceinline__ float roundtf(float x) { return __uint_as_float(f2tf32(x)); }

__device__ __forceinline__ void mma8(float* c, const uint32_t* a, uint32_t b0, uint32_t b1) {
    asm volatile(
        "mma.sync.aligned.m16n8k8.row.col.f32.tf32.tf32.f32 "
        "{%0,%1,%2,%3}, {%4,%5,%6,%7}, {%8,%9}, {%0,%1,%2,%3};\n"
        : "+f"(c[0]), "+f"(c[1]), "+f"(c[2]), "+f"(c[3])
        : "r"(a[0]), "r"(a[1]), "r"(a[2]), "r"(a[3]), "r"(b0), "r"(b1));
}

__device__ __forceinline__ void cp16(float* dst, const float* src) {
    uint32_t d = (uint32_t)__cvta_generic_to_shared(dst);
    asm volatile("cp.async.cg.shared.global [%0], [%1], 16;\n" :: "r"(d), "l"(src));
}
__device__ __forceinline__ void cp_commit() { asm volatile("cp.async.commit_group;\n"); }
__device__ __forceinline__ void cp_wait1()  { asm volatile("cp.async.wait_group 1;\n"); }

// ---------------- elementwise tf32 rounding (weights) -------------------------
__global__ void round_kernel(const float* __restrict__ src, float* __restrict__ dst, int n4)
{
    int i = blockIdx.x * blockDim.x + threadIdx.x;
    if (i < n4) {
        float4 v = ((const float4*)src)[i];
        v.x = roundtf(v.x); v.y = roundtf(v.y); v.z = roundtf(v.z); v.w = roundtf(v.w);
        ((float4*)dst)[i] = v;
    }
}

// ---------------- LayerNorm ----------------------------------------------------
// Yfull (optional) = res + LN(X)*g+b  (full precision)
// Yr    (optional) = tf32-rounded copy of the same value
__global__ void ln_kernel(const float* __restrict__ X, const float* __restrict__ gg,
                          const float* __restrict__ bb, const float* __restrict__ res,
                          float* __restrict__ Yfull, float* __restrict__ Yr)
{
    __shared__ float s1[256], s2[256];
    const int row = blockIdx.x;
    const int t = threadIdx.x;
    const float4* xr = (const float4*)(X + (size_t)row * DD);
    float4 v = xr[t];
    float s = v.x + v.y + v.z + v.w;
    float q = v.x*v.x + v.y*v.y + v.z*v.z + v.w*v.w;
    s1[t] = s; s2[t] = q;
    __syncthreads();
    #pragma unroll
    for (int o = 128; o > 0; o >>= 1) {
        if (t < o) { s1[t] += s1[t+o]; s2[t] += s2[t+o]; }
        __syncthreads();
    }
    const float mu  = s1[0] * (1.0f/1024.0f);
    const float var = s2[0] * (1.0f/1024.0f) - mu*mu;
    const float inv = rsqrtf(var + 1e-5f);
    float4 g4 = ((const float4*)gg)[t];
    float4 b4 = ((const float4*)bb)[t];
    float4 o;
    o.x = (v.x-mu)*inv*g4.x + b4.x;
    o.y = (v.y-mu)*inv*g4.y + b4.y;
    o.z = (v.z-mu)*inv*g4.z + b4.z;
    o.w = (v.w-mu)*inv*g4.w + b4.w;
    if (res) {
        float4 r = ((const float4*)(res + (size_t)row * DD))[t];
        o.x += r.x; o.y += r.y; o.z += r.z; o.w += r.w;
    }
    if (Yfull) ((float4*)(Yfull + (size_t)row * DD))[t] = o;
    if (Yr) {
        float4 rr = make_float4(roundtf(o.x), roundtf(o.y), roundtf(o.z), roundtf(o.w));
        ((float4*)(Yr + (size_t)row * DD))[t] = rr;
    }
}

// ---------------- in-place row softmax (row length 2048) ----------------------
__global__ void softmax_kernel(float* __restrict__ S)
{
    __shared__ float red[256];
    const size_t row = blockIdx.x;
    float* p = S + row * (size_t)TT;
    const int t = threadIdx.x;
    float v[8];
    float mx = -1e30f;
    #pragma unroll
    for (int i = 0; i < 8; i++) { v[i] = p[t + i * 256]; mx = fmaxf(mx, v[i]); }
    red[t] = mx; __syncthreads();
    #pragma unroll
    for (int o = 128; o > 0; o >>= 1) {
        if (t < o) red[t] = fmaxf(red[t], red[t+o]);
        __syncthreads();
    }
    mx = red[0];
    __syncthreads();
    float sum = 0.0f;
    #pragma unroll
    for (int i = 0; i < 8; i++) { v[i] = __expf(v[i] - mx); sum += v[i]; }
    red[t] = sum; __syncthreads();
    #pragma unroll
    for (int o = 128; o > 0; o >>= 1) {
        if (t < o) red[t] += red[t+o];
        __syncthreads();
    }
    const float inv = 1.0f / red[0];
    #pragma unroll
    for (int i = 0; i < 8; i++) p[t + i * 256] = v[i] * inv;
}

// =====================================================================
// Unified tf32 tensor-core GEMM, 3-stage cp.async pipeline, 1 sync/iter.
//   C[r][c] = act( scale * sum_k A[r][k]*B(k,c) + bias[c] ) + residual[r][c]
// Operands are PRE-ROUNDED to tf32 (except CVTA: cvt A-fragments inline).
// BM=128, BK=32, 256 threads, warp grid 2(m) x 4(n).
// BMODE: 0 -> B row-major [K,N]
//        1 -> B is [H, K, 64], global col = h*64+p
//        2 -> B given as [N, K] row-major (smem tile n-major)
// outRound: store tf32-rounded result (for buffers feeding further GEMMs).
// =====================================================================
template<int BN, int BMODE, bool CVTA>
__global__ void __launch_bounds__(256, 2) mma_gemm(
    const float* __restrict__ A, int lda, size_t aOffB, size_t aOffH,
    const float* __restrict__ B, int ldb, size_t bOffB, size_t bOffH,
    float*       __restrict__ C, int ldc, size_t cOffB, size_t cOffH,
    int K, const float* __restrict__ bias, const float* __restrict__ residual,
    int act, float scale, int outRound)
{
    constexpr int BM = 128, BK = 32, STAGES = 3;
    constexpr int NT = BN / 32;
    constexpr int WN = BN / 4;
    constexpr int AROW = BK + 4;                    // 36
    constexpr int A_STAGE = BM * AROW;
    constexpr int BROW = (BMODE == 2) ? (BK + 4) : (BN + 8);   // 36 | 136/72
    constexpr int B_STAGE = (BMODE == 2) ? (BN * BROW) : (BK * BROW);

    extern __shared__ float sm[];
    float* AsBase = sm;
    float* BsBase = sm + STAGES * A_STAGE;

    const int tid  = threadIdx.x;
    const int lane = tid & 31;
    const int warp = tid >> 5;
    const int g  = lane >> 2;
    const int tq = lane & 3;
    const int wmBase = (warp & 1) * 64;
    const int wnBase = (warp >> 1) * WN;

    const int row0 = blockIdx.y * BM;
    const int col0 = blockIdx.x * BN;

    const int zb = blockIdx.z >> 4, zh = blockIdx.z & 15;
    A += (size_t)zb * aOffB + (size_t)zh * aOffH;
    B += (size_t)zb * bOffB + (size_t)zh * bOffH;
    C += (size_t)zb * cOffB + (size_t)zh * cOffH;

    const int nT = K >> 5;

    auto issueA = [&](int t, float* dst) {
        const float* Ak = A + (size_t)row0 * lda + t * BK;
        #pragma unroll
        for (int p = 0; p < 4; p++) {
            int chunk = tid + 256 * p;
            int r = chunk >> 3, c = (chunk & 7) * 4;
            cp16(dst + r * AROW + c, Ak + (size_t)r * lda + c);
        }
    };
    auto issueB = [&](int t, float* dst) {
        if (BMODE == 2) {
            const float* Bk = B + (size_t)col0 * ldb + t * BK;
            #pragma unroll
            for (int p = 0; p < 4; p++) {
                int chunk = tid + 256 * p;
                int r = chunk >> 3, c = (chunk & 7) * 4;
                cp16(dst + r * BROW + c, Bk + (size_t)r * ldb + c);
            }
        } else if (BMODE == 0) {
            constexpr int P   = (BN == 128) ? 4 : 2;
            constexpr int CSH = (BN == 128) ? 5 : 4;
            constexpr int CMK = (BN == 128) ? 31 : 15;
            const float* Bk = B + (size_t)(t * BK) * ldb + col0;
            #pragma unroll
            for (int p = 0; p < P; p++) {
                int chunk = tid + 256 * p;
                int k = chunk >> CSH, c = (chunk & CMK) * 4;
                cp16(dst + k * BROW + c, Bk + (size_t)k * ldb + c);
            }
        } else { // BMODE 1, BN==128
            #pragma unroll
            for (int p = 0; p < 4; p++) {
                int chunk = tid + 256 * p;
                int k = chunk >> 5, c = (chunk & 31) * 4;
                int col = col0 + c;
                const float* src = B + (size_t)(col >> 6) * ((size_t)K * 64)
                                     + (size_t)(t * BK + k) * 64 + (col & 63);
                cp16(dst + k * BROW + c, src);
            }
        }
    };

    float acc[4][NT][4];
    #pragma unroll
    for (int i = 0; i < 4; i++)
        #pragma unroll
        for (int j = 0; j < NT; j++)
            #pragma unroll
            for (int l = 0; l < 4; l++) acc[i][j][l] = 0.0f;

    #pragma unroll
    for (int t = 0; t < STAGES - 1; t++) {
        if (t < nT) { issueA(t, AsBase + t * A_STAGE); issueB(t, BsBase + t * B_STAGE); }
        cp_commit();
    }

    int s = 0;
    for (int t = 0; t < nT; t++) {
        cp_wait1();
        __syncthreads();

        const float* As  = AsBase + s * A_STAGE;
        const float* Bsm = BsBase + s * B_STAGE;

        #pragma unroll
        for (int ks = 0; ks < 4; ks++) {
            const int kb = ks * 8;
            uint32_t af[4][4];
            #pragma unroll
            for (int mi = 0; mi < 4; mi++) {
                int r = wmBase + mi * 16 + g;
                float a0 = As[(size_t)r       * AROW + kb + tq];
                float a1 = As[(size_t)(r + 8) * AROW + kb + tq];
                float a2 = As[(size_t)r       * AROW + kb + tq + 4];
                float a3 = As[(size_t)(r + 8) * AROW + kb + tq + 4];
                if (CVTA) {
                    af[mi][0] = f2tf32(a0); af[mi][1] = f2tf32(a1);
                    af[mi][2] = f2tf32(a2); af[mi][3] = f2tf32(a3);
                } else {
                    af[mi][0] = __float_as_uint(a0); af[mi][1] = __float_as_uint(a1);
                    af[mi][2] = __float_as_uint(a2); af[mi][3] = __float_as_uint(a3);
                }
            }
            #pragma unroll
            for (int ni = 0; ni < NT; ni++) {
                int n = wnBase + ni * 8 + g;
                uint32_t b0, b1;
                if (BMODE == 2) {
                    b0 = __float_as_uint(Bsm[(size_t)n * BROW + kb + tq]);
                    b1 = __float_as_uint(Bsm[(size_t)n * BROW + kb + tq + 4]);
                } else {
                    b0 = __float_as_uint(Bsm[(size_t)(kb + tq)     * BROW + n]);
                    b1 = __float_as_uint(Bsm[(size_t)(kb + tq + 4) * BROW + n]);
                }
                #pragma unroll
                for (int mi = 0; mi < 4; mi++)
                    mma8(acc[mi][ni], af[mi], b0, b1);
            }
        }

        // next issue: writes stage (t+2)%3, last read at iter t-1; the sync at
        // the top of THIS iteration already ordered those reads. One sync/iter.
        int tn = t + STAGES - 1;
        if (tn < nT) {
            int sn = tn - (tn / STAGES) * STAGES;
            issueA(tn, AsBase + sn * A_STAGE);
            issueB(tn, BsBase + sn * B_STAGE);
        }
        cp_commit();

        s++; if (s == STAGES) s = 0;
    }

    // ---------------- epilogue ----------------
    #pragma unroll
    for (int mi = 0; mi < 4; mi++) {
        int r0 = row0 + wmBase + mi * 16 + g;
        #pragma unroll
        for (int ni = 0; ni < NT; ni++) {
            int col = col0 + wnBase + ni * 8 + 2 * tq;
            float b0 = 0.0f, b1 = 0.0f;
            if (bias) { b0 = bias[col]; b1 = bias[col + 1]; }
            #pragma unroll
            for (int half = 0; half < 2; half++) {
                int r = r0 + half * 8;
                float x0 = acc[mi][ni][half*2 + 0] * scale + b0;
                float x1 = acc[mi][ni][half*2 + 1] * scale + b1;
                if (act) { x0 = gelu_f(x0); x1 = gelu_f(x1); }
                if (residual) {
                    float2 rr = *(const float2*)(residual + (size_t)r * ldc + col);
                    x0 += rr.x; x1 += rr.y;
                }
                if (outRound) { x0 = roundtf(x0); x1 = roundtf(x1); }
                *(float2*)(C + (size_t)r * ldc + col) = make_float2(x0, x1);
            }
        }
    }
}

// smem sizes (bytes)
static constexpr int STAGES_H = 3;
static constexpr size_t smemBytes(int BN, int BMODE) {
    size_t aStage = 128 * 36;
    size_t bStage = (BMODE == 2) ? (size_t)BN * 36 : (size_t)32 * (BN + 8);
    return STAGES_H * (aStage + bStage) * 4;
}

// -----------------------------------------------------------------------------
extern "C" void kernel_launch(void* const* d_in, const int* in_sizes, int n_in,
                              void* d_out, int out_size)
{
    const float* X      = (const float*)d_in[0];
    const float* WQ     = (const float*)d_in[1];
    const float* WK     = (const float*)d_in[2];
    const float* WV     = (const float*)d_in[3];
    const float* WO     = (const float*)d_in[4];
    const float* attn_g = (const float*)d_in[5];
    const float* attn_b = (const float*)d_in[6];
    const float* ff_g   = (const float*)d_in[7];
    const float* ff_b   = (const float*)d_in[8];
    const float* fW1    = (const float*)d_in[9];
    const float* fb1    = (const float*)d_in[10];
    const float* fW2    = (const float*)d_in[11];
    const float* fb2    = (const float*)d_in[12];

    float* out1 = (float*)d_out;                               // [B,T,D]
    float* attn = (float*)d_out + (size_t)BB * TT * DD;        // [B,H,T,T]

    float *nX, *Q, *K_, *V, *NV, *SS, *PRE, *PREr, *HID, *WTS;
    cudaGetSymbolAddress((void**)&nX,   g_nX);
    cudaGetSymbolAddress((void**)&Q,    g_Q);
    cudaGetSymbolAddress((void**)&K_,   g_K);
    cudaGetSymbolAddress((void**)&V,    g_V);
    cudaGetSymbolAddress((void**)&NV,   g_NV);
    cudaGetSymbolAddress((void**)&SS,   g_SS);
    cudaGetSymbolAddress((void**)&PRE,  g_PRE);
    cudaGetSymbolAddress((void**)&PREr, g_PREr);
    cudaGetSymbolAddress((void**)&HID,  g_HID);
    cudaGetSymbolAddress((void**)&WTS,  g_WTS);

    const size_t M1 = 1024*1024;
    float* WQr  = WTS;
    float* WKr  = WTS + 1*M1;
    float* WVr  = WTS + 2*M1;
    float* WOr  = WTS + 3*M1;
    float* fW1r = WTS + 4*M1;
    float* fW2r = WTS + 8*M1;

    static bool attrDone = false;
    if (!attrDone) {
        cudaFuncSetAttribute(mma_gemm<128,1,false>, cudaFuncAttributeMaxDynamicSharedMemorySize, (int)smemBytes(128,1));
        cudaFuncSetAttribute(mma_gemm<128,2,false>, cudaFuncAttributeMaxDynamicSharedMemorySize, (int)smemBytes(128,2));
        cudaFuncSetAttribute(mma_gemm<64,0,true>,   cudaFuncAttributeMaxDynamicSharedMemorySize, (int)smemBytes(64,0));
        cudaFuncSetAttribute(mma_gemm<128,0,false>, cudaFuncAttributeMaxDynamicSharedMemorySize, (int)smemBytes(128,0));
        attrDone = true;
    }

    const size_t TT2 = (size_t)TT * TT;
    const size_t TD  = (size_t)TT * DD;

    // 0. round weights to tf32 (once per launch; graph replays identical work)
    round_kernel<<<(1*M1/4+255)/256, 256>>>(WQ,  WQr,  (int)(1*M1/4));
    round_kernel<<<(1*M1/4+255)/256, 256>>>(WK,  WKr,  (int)(1*M1/4));
    round_kernel<<<(1*M1/4+255)/256, 256>>>(WV,  WVr,  (int)(1*M1/4));
    round_kernel<<<(1*M1/4+255)/256, 256>>>(WO,  WOr,  (int)(1*M1/4));
    round_kernel<<<(4*M1/4+255)/256, 256>>>(fW1, fW1r, (int)(4*M1/4));
    round_kernel<<<(4*M1/4+255)/256, 256>>>(fW2, fW2r, (int)(4*M1/4));

    // 1. nX = round(LN(X))
    ln_kernel<<<ROWS, 256>>>(X, attn_g, attn_b, nullptr, nullptr, nX);

    // 2-4. Q/K/V = nX @ W{Q,K,V}  (rounded outputs)
    dim3 gQKV(DD/128, ROWS/128, 1);
    mma_gemm<128,1,false><<<gQKV, 256, smemBytes(128,1)>>>(nX, DD, 0,0, WQr, 0, 0,0, Q,  DD, 0,0, DD, nullptr, nullptr, 0, 1.0f, 1);
    mma_gemm<128,1,false><<<gQKV, 256, smemBytes(128,1)>>>(nX, DD, 0,0, WKr, 0, 0,0, K_, DD, 0,0, DD, nullptr, nullptr, 0, 1.0f, 1);
    mma_gemm<128,1,false><<<gQKV, 256, smemBytes(128,1)>>>(nX, DD, 0,0, WVr, 0, 0,0, V,  DD, 0,0, DD, nullptr, nullptr, 0, 1.0f, 1);

    // 5. scores -> attn (full precision), 6. softmax in place
    mma_gemm<128,2,false><<<dim3(TT/128, TT/128, BB*HH), 256, smemBytes(128,2)>>>(
        K_, DD, TD, 64,
        Q,  DD, TD, 64,
        attn, TT, 16*TT2, TT2,
        PP, nullptr, nullptr, 0, 0.125f, 0);
    softmax_kernel<<<BB*HH*TT, 256>>>(attn);

    // 7. NV = attn @ V  (cvt attn inline; rounded output)
    mma_gemm<64,0,true><<<dim3(1, TT/128, BB*HH), 256, smemBytes(64,0)>>>(
        attn, TT, 16*TT2, TT2,
        V,    DD, TD, 64,
        NV,   DD, TD, 64,
        TT, nullptr, nullptr, 0, 1.0f, 1);

    // 8. SS = NV @ WO (full)
    mma_gemm<128,0,false><<<dim3(DD/128, ROWS/128, 1), 256, smemBytes(128,0)>>>(
        NV, DD, 0,0, WOr, DD, 0,0, SS, DD, 0,0, DD, nullptr, nullptr, 0, 1.0f, 0);

    // 9. PRE = X + LN(SS)  (full + rounded copy)
    ln_kernel<<<ROWS, 256>>>(SS, ff_g, ff_b, X, PRE, PREr);

    // 10. HID = round(gelu(PREr @ fW1 + fb1))
    mma_gemm<128,0,false><<<dim3(FFD/128, ROWS/128, 1), 256, smemBytes(128,0)>>>(
        PREr, DD, 0,0, fW1r, FFD, 0,0, HID, FFD, 0,0, DD, fb1, nullptr, 1, 1.0f, 1);

    // 11. out1 = HID @ fW2 + fb2 + PRE (full)
    mma_gemm<128,0,false><<<dim3(DD/128, ROWS/128, 1), 256, smemBytes(128,0)>>>(
        HID, FFD, 0,0, fW2r, DD, 0,0, out1, DD, 0,0, FFD, fb2, PRE, 0, 1.0f, 0);
}